// round 14
// baseline (speedup 1.0000x reference)
#include <cuda_runtime.h>
#include <cuda_bf16.h>
#include <cstdint>

#define KN     8192
#define KD     8
#define NTHR   256
#define IPT    4
#define ITILE  1024          // i-rows per dom strip (IPT * NTHR)
#define TJ     64            // j-rows per dom tile
#define NSEG   8
#define SEGSZ  1024
#define NTILES 576           // per matrix: sum_{ti=0..7} 16*(ti+1)

// Device-global scratch. Statics start zeroed; every consumer re-zeroes or
// fully overwrites what it reads -> graph replays are deterministic.
__device__ unsigned       g_keys[16][KN];   // [m*8+d] segment-sorted keys
__device__ int            g_kidx[16][KN];   // original row id per seg-sorted pos
__device__ uint4          g_row16[2][KN];   // per-ORIGINAL-row packed fp16 codes d1..d7 (+pad0)
__device__ int            g_perm[2][KN];    // d0-rank -> original row
__device__ int            g_counts[2 * KN]; // per sorted-row "neg" counts
__device__ int            g_hd[KN];         // signed diff histogram (A minus B)
__device__ unsigned       g_done;           // dom completion tickets

__device__ __forceinline__ unsigned f2sortable(float f) {
    unsigned u = __float_as_uint(f);
    return (u & 0x80000000u) ? ~u : (u | 0x80000000u);
}

// packed fp16x2 add (sign-exact for rank-code differences)
__device__ __forceinline__ unsigned hadd2(unsigned a, unsigned b) {
    unsigned d;
    asm("add.rn.f16x2 %0, %1, %2;" : "=r"(d) : "r"(a), "r"(b));
    return d;
}

// ---------------------------------------------------------------------------
// S1) bitonic-sort 1024-element segments, 256 threads x 4 elements.
//     Distances >=256: in-register; 32..128: smem; <=16: shfl.
// ---------------------------------------------------------------------------
__global__ __launch_bounds__(256) void kdm_sort_seg(const float* __restrict__ X,
                                                    const float* __restrict__ Xh) {
    const int md = blockIdx.y;
    const int d  = md & 7;
    const float* __restrict__ src = (md >> 3) ? Xh : X;
    __shared__ unsigned long long s[SEGSZ];   // 8 KB
    const int t  = threadIdx.x;
    const int e0 = blockIdx.x * SEGSZ;

    unsigned long long v[4];
    #pragma unroll
    for (int q = 0; q < 4; q++) {
        const int idx = q * 256 + t;
        v[q] = ((unsigned long long)f2sortable(src[(size_t)(e0 + idx) * KD + d]) << 32)
               | (unsigned)(e0 + idx);
    }

    #pragma unroll
    for (int k = 2; k <= SEGSZ; k <<= 1) {
        int j = k >> 1;
        #pragma unroll
        for (int jj = 512; jj >= 256; jj >>= 1) {
            if (jj <= (k >> 1)) {
                const int dq = jj >> 8;
                #pragma unroll
                for (int qa = 0; qa < 4; qa++) {
                    if ((qa & dq) == 0) {
                        const int qb = qa | dq;
                        const bool up = (((qa * 256 + t) & k) == 0);
                        const unsigned long long a = v[qa], b = v[qb];
                        if ((a > b) == up) { v[qa] = b; v[qb] = a; }
                    }
                }
                j = jj >> 1;
            }
        }
        while (j >= 32) {
            #pragma unroll
            for (int q = 0; q < 4; q++) s[q * 256 + t] = v[q];
            __syncthreads();
            unsigned long long p[4];
            #pragma unroll
            for (int q = 0; q < 4; q++) p[q] = s[q * 256 + (t ^ j)];
            __syncthreads();
            #pragma unroll
            for (int q = 0; q < 4; q++) {
                const bool up   = (((q * 256 + t) & k) == 0);
                const bool low  = (t & j) == 0;
                const bool keepmin = (low == up);
                const bool omin = (p[q] < v[q]);
                v[q] = (keepmin == omin) ? p[q] : v[q];
            }
            j >>= 1;
        }
        #pragma unroll
        for (int jj = 16; jj >= 1; jj >>= 1) {
            if (jj <= (k >> 1)) {
                #pragma unroll
                for (int q = 0; q < 4; q++) {
                    const unsigned long long o = __shfl_xor_sync(0xffffffffu, v[q], jj);
                    const bool up   = (((q * 256 + t) & k) == 0);
                    const bool low  = (t & jj) == 0;
                    const bool keepmin = (low == up);
                    const bool omin = (o < v[q]);
                    v[q] = (keepmin == omin) ? o : v[q];
                }
            }
        }
    }

    #pragma unroll
    for (int q = 0; q < 4; q++) {
        const unsigned long long r = v[q];
        g_keys[md][e0 + q * 256 + t] = (unsigned)(r >> 32);
        g_kidx[md][e0 + q * 256 + t] = (int)(unsigned)r;
    }
}

// ---------------------------------------------------------------------------
// S2) global rank via cross-segment binary search. d==0 writes the d0-rank
//     permutation; d>=1 writes the biased fp16 code straight into the row's
//     packed slot (no separate pack kernel). PDL-synced on sort.
// ---------------------------------------------------------------------------
__global__ __launch_bounds__(256) void kdm_rank() {
    const int md = blockIdx.y;
    const int m  = md >> 3;
    const int d  = md & 7;
    const int e  = blockIdx.x * 256 + threadIdx.x;
    const int s  = e >> 10;
    const int pos = e & (SEGSZ - 1);

    cudaGridDependencySynchronize();   // wait for kdm_sort_seg

    __shared__ unsigned sk[KN];   // 32 KB
    for (int k = threadIdx.x; k < KN; k += 256) sk[k] = g_keys[md][k];
    __syncthreads();

    const unsigned key = sk[e];
    int rank = pos;
    #pragma unroll
    for (int t = 0; t < NSEG; t++) {
        if (t == s) continue;
        const unsigned* seg = sk + t * SEGSZ;
        int lo = 0, hi = SEGSZ;
        if (t < s) {  // count <= key
            while (lo < hi) { const int mid = (lo + hi) >> 1; if (seg[mid] <= key) lo = mid + 1; else hi = mid; }
        } else {      // count < key
            while (lo < hi) { const int mid = (lo + hi) >> 1; if (seg[mid] <  key) lo = mid + 1; else hi = mid; }
        }
        rank += lo;
    }

    const int row = g_kidx[md][e];
    if (d == 0) {
        g_perm[m][rank] = row;                       // d0-rank -> row
    } else {
        // halves 0..6 hold d1..d7; half 7 is pad (never written, stays 0)
        reinterpret_cast<unsigned short*>(&g_row16[m][row])[d - 1] =
            (unsigned short)(rank + 0x400);
    }
}

// ---------------------------------------------------------------------------
// D) triangular dominance on d0-rank order via perm gather; thread owns 4
//    i-rows; strip ti has 16*(ti+1) j-tiles of 64; start(ti) = 8*ti*(ti+1).
//    The LAST block to finish runs the fused histogram + W1 finalize.
// ---------------------------------------------------------------------------
__global__ __launch_bounds__(NTHR, 6) void kdm_dom(float* __restrict__ out) {
    const int m = blockIdx.y;
    const int b = blockIdx.x;
    int ti = (int)(sqrtf((float)b * 0.125f + 0.25f));
    while (ti > 0 && 8 * ti * (ti + 1) > b) --ti;
    while (8 * (ti + 1) * (ti + 2) <= b) ++ti;
    const int tj = b - 8 * ti * (ti + 1);
    const int i0 = ti << 10;
    const int j0 = tj << 6;
    const int tid = threadIdx.x;
    const int ib = i0 + tid;

    cudaGridDependencySynchronize();   // wait for kdm_rank

    __shared__ uint4 sj[TJ];    // 1 KB, fp16-negated j-rows
    if (tid < TJ) {
        uint4 v = g_row16[m][g_perm[m][j0 + tid]];
        v.x ^= 0x80008000u; v.y ^= 0x80008000u;
        v.z ^= 0x80008000u; v.w ^= 0x80008000u;
        sj[tid] = v;
    }

    uint4 a[IPT];
    #pragma unroll
    for (int p = 0; p < IPT; p++) a[p] = g_row16[m][g_perm[m][ib + p * NTHR]];
    __syncthreads();

    unsigned neg[IPT] = {0, 0, 0, 0};

    if (j0 + TJ <= i0) {
        #pragma unroll 4
        for (int j = 0; j < TJ; j++) {
            const uint4 bv = sj[j];
            #pragma unroll
            for (int p = 0; p < IPT; p++) {
                const unsigned x0 = hadd2(a[p].x, bv.x);
                const unsigned x1 = hadd2(a[p].y, bv.y);
                const unsigned x2 = hadd2(a[p].z, bv.z);
                const unsigned x3 = hadd2(a[p].w, bv.w);
                const unsigned o  = x0 | x1 | x2;
                const unsigned sb = (o | x3) & 0x80008000u;
                if (sb) neg[p]++;
            }
        }
    } else {
        int lim[IPT];
        #pragma unroll
        for (int p = 0; p < IPT; p++) lim[p] = ib + p * NTHR - j0;
        #pragma unroll 4
        for (int j = 0; j < TJ; j++) {
            const uint4 bv = sj[j];
            #pragma unroll
            for (int p = 0; p < IPT; p++) {
                const unsigned x0 = hadd2(a[p].x, bv.x);
                const unsigned x1 = hadd2(a[p].y, bv.y);
                const unsigned x2 = hadd2(a[p].z, bv.z);
                const unsigned x3 = hadd2(a[p].w, bv.w);
                const unsigned o  = x0 | x1 | x2;
                const unsigned sb = (o | x3) & 0x80008000u;
                neg[p] += min(sb, 1u) | (unsigned)(j >= lim[p]);
            }
        }
    }

    #pragma unroll
    for (int p = 0; p < IPT; p++)
        atomicAdd(&g_counts[m * KN + ib + p * NTHR], (int)neg[p]);

    // ---- completion ticket; last block runs the finale ----
    __syncthreads();
    __shared__ unsigned s_ticket;
    if (tid == 0) {
        __threadfence();                         // counts visible before ticket
        s_ticket = atomicAdd(&g_done, 1u);
    }
    __syncthreads();
    if (s_ticket != 2 * NTILES - 1) return;
    __threadfence();                             // acquire all counts

    // ---- finale: histogram + W1 scan (256 threads, single block) ----
    {
        #pragma unroll
        for (int k = 0; k < 64; k++) {
            const int slot = k * 256 + tid;
            const int neg2 = g_counts[slot];
            g_counts[slot] = 0;
            const int i = slot & (KN - 1);
            const int v = (((i >> 10) + 1) << 10) - neg2;   // dominated count
            atomicAdd(&g_hd[v], (slot >= KN) ? -1 : 1);
        }
    }
    __syncthreads();
    __threadfence();

    __shared__ int wsum[8], asum[8];
    const int lane = tid & 31, wid = tid >> 5;
    const int base = tid * 32;
    int d2[32], tot = 0;
    #pragma unroll
    for (int k = 0; k < 32; k++) {
        d2[k] = g_hd[base + k];
        g_hd[base + k] = 0;
        tot += d2[k];
    }

    int v = tot;
    #pragma unroll
    for (int off = 1; off < 32; off <<= 1) {
        const int n = __shfl_up_sync(0xffffffffu, v, off);
        if (lane >= off) v += n;
    }
    if (lane == 31) wsum[wid] = v;
    __syncthreads();
    if (tid == 0) {
        int run = 0;
        #pragma unroll
        for (int w = 0; w < 8; w++) { const int x = wsum[w]; wsum[w] = run; run += x; }
    }
    __syncthreads();

    const int excl = v - tot + wsum[wid];
    int run = excl, acc = 0;
    #pragma unroll
    for (int k = 0; k < 32; k++) {
        run += d2[k];
        acc += (run >= 0) ? run : -run;
    }

    #pragma unroll
    for (int off = 16; off; off >>= 1) acc += __shfl_down_sync(0xffffffffu, acc, off);
    if (lane == 0) asum[wid] = acc;
    __syncthreads();
    if (tid == 0) {
        int r = 0;
        #pragma unroll
        for (int w = 0; w < 8; w++) r += asum[w];
        out[0] = (float)r / ((float)KN * (float)(KN - 1));
        g_done = 0;   // reset for next graph replay
    }
}

// ---------------------------------------------------------------------------
// Host: 3-kernel chain with PDL.
// ---------------------------------------------------------------------------
template <typename F, typename... Args>
static void launch_pdl(F f, dim3 grid, dim3 block, Args... args) {
    cudaLaunchConfig_t cfg = {};
    cfg.gridDim  = grid;
    cfg.blockDim = block;
    cfg.dynamicSmemBytes = 0;
    cfg.stream = 0;
    cudaLaunchAttribute attr[1];
    attr[0].id = cudaLaunchAttributeProgrammaticStreamSerialization;
    attr[0].val.programmaticStreamSerializationAllowed = 1;
    cfg.attrs = attr;
    cfg.numAttrs = 1;
    cudaLaunchKernelEx(&cfg, f, args...);
}

extern "C" void kernel_launch(void* const* d_in, const int* in_sizes, int n_in,
                              void* d_out, int out_size) {
    const float* X  = (const float*)d_in[0];
    const float* Xh = (const float*)d_in[1];
    float* out = (float*)d_out;

    kdm_sort_seg<<<dim3(NSEG, 16), 256>>>(X, Xh);
    launch_pdl(kdm_rank, dim3(KN / 256, 16), dim3(256));
    launch_pdl(kdm_dom,  dim3(NTILES, 2),    dim3(NTHR), out);
}

// round 15
// speedup vs baseline: 1.3964x; 1.3964x over previous
#include <cuda_runtime.h>
#include <cuda_bf16.h>
#include <cstdint>

#define KN     8192
#define KD     8
#define NSEG   8
#define SEGSZ  1024
#define NTILE  64            // 128-row j-tiles per matrix
#define TW     4             // words per 128-bit mask
#define DOMB   288           // per matrix: sum_{s=0..7}(8s+8)

// Device-global scratch. Statics start zeroed; every consumer re-zeroes or
// fully overwrites what it reads -> graph replays are deterministic.
__device__ unsigned       g_keys[16][KN];           // [m*8+d] segment-sorted keys
__device__ int            g_kidx[16][KN];           // original row id per seg-sorted pos
__device__ unsigned short g_rank[2][KN][8];         // raw per-dim rank per ORIGINAL row
__device__ int            g_perm[2][KN];            // d0-rank -> original row
__device__ unsigned short g_sr[2][NTILE][7][128];   // per tile/dim: sorted d-ranks
__device__ unsigned       g_B[2][NTILE][7][129][TW];// cumulative bitmask tables
__device__ int            g_counts[2 * KN];         // per d0-rank dominated counts
__device__ int            g_hd[KN];                 // signed diff histogram (A - B)
__device__ unsigned       g_ctr;                    // finh arrival counter

__device__ __forceinline__ unsigned f2sortable(float f) {
    unsigned u = __float_as_uint(f);
    return (u & 0x80000000u) ? ~u : (u | 0x80000000u);
}

// ---------------------------------------------------------------------------
// S1) bitonic-sort 1024-element segments, 256 threads x 4 elements (proven).
// ---------------------------------------------------------------------------
__global__ __launch_bounds__(256) void kdm_sort_seg(const float* __restrict__ X,
                                                    const float* __restrict__ Xh) {
    const int md = blockIdx.y;
    const int d  = md & 7;
    const float* __restrict__ src = (md >> 3) ? Xh : X;
    __shared__ unsigned long long s[SEGSZ];   // 8 KB
    const int t  = threadIdx.x;
    const int e0 = blockIdx.x * SEGSZ;

    unsigned long long v[4];
    #pragma unroll
    for (int q = 0; q < 4; q++) {
        const int idx = q * 256 + t;
        v[q] = ((unsigned long long)f2sortable(src[(size_t)(e0 + idx) * KD + d]) << 32)
               | (unsigned)(e0 + idx);
    }

    #pragma unroll
    for (int k = 2; k <= SEGSZ; k <<= 1) {
        int j = k >> 1;
        #pragma unroll
        for (int jj = 512; jj >= 256; jj >>= 1) {
            if (jj <= (k >> 1)) {
                const int dq = jj >> 8;
                #pragma unroll
                for (int qa = 0; qa < 4; qa++) {
                    if ((qa & dq) == 0) {
                        const int qb = qa | dq;
                        const bool up = (((qa * 256 + t) & k) == 0);
                        const unsigned long long a = v[qa], b = v[qb];
                        if ((a > b) == up) { v[qa] = b; v[qb] = a; }
                    }
                }
                j = jj >> 1;
            }
        }
        while (j >= 32) {
            #pragma unroll
            for (int q = 0; q < 4; q++) s[q * 256 + t] = v[q];
            __syncthreads();
            unsigned long long p[4];
            #pragma unroll
            for (int q = 0; q < 4; q++) p[q] = s[q * 256 + (t ^ j)];
            __syncthreads();
            #pragma unroll
            for (int q = 0; q < 4; q++) {
                const bool up   = (((q * 256 + t) & k) == 0);
                const bool low  = (t & j) == 0;
                const bool keepmin = (low == up);
                const bool omin = (p[q] < v[q]);
                v[q] = (keepmin == omin) ? p[q] : v[q];
            }
            j >>= 1;
        }
        #pragma unroll
        for (int jj = 16; jj >= 1; jj >>= 1) {
            if (jj <= (k >> 1)) {
                #pragma unroll
                for (int q = 0; q < 4; q++) {
                    const unsigned long long o = __shfl_xor_sync(0xffffffffu, v[q], jj);
                    const bool up   = (((q * 256 + t) & k) == 0);
                    const bool low  = (t & jj) == 0;
                    const bool keepmin = (low == up);
                    const bool omin = (o < v[q]);
                    v[q] = (keepmin == omin) ? o : v[q];
                }
            }
        }
    }

    #pragma unroll
    for (int q = 0; q < 4; q++) {
        const unsigned long long r = v[q];
        g_keys[md][e0 + q * 256 + t] = (unsigned)(r >> 32);
        g_kidx[md][e0 + q * 256 + t] = (int)(unsigned)r;
    }
}

// ---------------------------------------------------------------------------
// S2) global rank via cross-segment binary search (proven while-loop form).
//     Writes raw rank per (row, d); d==0 also writes the d0 permutation.
// ---------------------------------------------------------------------------
__global__ __launch_bounds__(256) void kdm_rank() {
    const int md = blockIdx.y;
    const int m  = md >> 3;
    const int d  = md & 7;
    const int e  = blockIdx.x * 256 + threadIdx.x;
    const int s  = e >> 10;
    const int pos = e & (SEGSZ - 1);

    cudaGridDependencySynchronize();

    __shared__ unsigned sk[KN];   // 32 KB
    for (int k = threadIdx.x; k < KN; k += 256) sk[k] = g_keys[md][k];
    __syncthreads();

    const unsigned key = sk[e];
    int rank = pos;
    #pragma unroll
    for (int t = 0; t < NSEG; t++) {
        if (t == s) continue;
        const unsigned* seg = sk + t * SEGSZ;
        int lo = 0, hi = SEGSZ;
        if (t < s) {  // count <= key
            while (lo < hi) { const int mid = (lo + hi) >> 1; if (seg[mid] <= key) lo = mid + 1; else hi = mid; }
        } else {      // count < key
            while (lo < hi) { const int mid = (lo + hi) >> 1; if (seg[mid] <  key) lo = mid + 1; else hi = mid; }
        }
        rank += lo;
    }

    const int row = g_kidx[md][e];
    g_rank[m][row][d] = (unsigned short)rank;
    if (d == 0) g_perm[m][rank] = row;
}

// ---------------------------------------------------------------------------
// P) per (tile, dim): sorted d-rank list + cumulative bitmask table.
//    grid = (NTILE, 7, 2), block = 128. Bit k of B[p] = [tile-local d-order
//    position of row k  <  p]; B[128] = all ones.
// ---------------------------------------------------------------------------
__global__ __launch_bounds__(128) void kdm_prep() {
    const int tt = blockIdx.x;
    const int d  = blockIdx.y + 1;       // dims 1..7
    const int m  = blockIdx.z;
    const int k  = threadIdx.x;

    cudaGridDependencySynchronize();

    __shared__ unsigned short ranks[128];
    __shared__ unsigned char  pos[128];

    const int row = g_perm[m][tt * 128 + k];
    const unsigned short myrank = g_rank[m][row][d];
    ranks[k] = myrank;
    __syncthreads();

    int o = 0;
    #pragma unroll 8
    for (int r = 0; r < 128; r++) o += (ranks[r] < myrank);
    pos[k] = (unsigned char)o;
    g_sr[m][tt][d - 1][o] = myrank;      // scatter -> ascending list
    __syncthreads();

    // thread p = k builds B[p] (4 words)
    unsigned acc[TW] = {0, 0, 0, 0};
    #pragma unroll 8
    for (int r = 0; r < 128; r++)
        acc[r >> 5] |= (unsigned)(pos[r] < k) << (r & 31);
    #pragma unroll
    for (int w = 0; w < TW; w++) g_B[m][tt][d - 1][k][w] = acc[w];
    if (k == 0) {
        #pragma unroll
        for (int w = 0; w < TW; w++) g_B[m][tt][d - 1][128][w] = 0xFFFFFFFFu;
    }
}

// ---------------------------------------------------------------------------
// D) bitset dominance. Block = (i-strip of 1024 d0-ranks) x (one 128-row
//    j-tile). Strip s has 8s+8 tiles; start(s) = 4s(s+1). Per i: 7 searches
//    -> 7 mask rows AND'd with the d0 prefix mask, popcounted.
// ---------------------------------------------------------------------------
__global__ __launch_bounds__(256) void kdm_dom() {
    const int m = blockIdx.y;
    int bx = blockIdx.x;
    int s = 0;
    while (4 * (s + 1) * (s + 2) <= bx) s++;
    const int tt = bx - 4 * s * (s + 1);
    const int tid = threadIdx.x;

    cudaGridDependencySynchronize();

    __shared__ unsigned        sB[7][129][TW];   // 14448 B
    __shared__ unsigned short  ssr[7][128];      // 1792 B

    {   // cooperative slab load (contiguous per (m,tt))
        const unsigned* gb = &g_B[m][tt][0][0][0];
        unsigned* sb = &sB[0][0][0];
        for (int idx = tid; idx < 7 * 129 * TW; idx += 256) sb[idx] = gb[idx];
        const unsigned* gr = (const unsigned*)&g_sr[m][tt][0][0];
        unsigned* sr = (unsigned*)&ssr[0][0];
        for (int idx = tid; idx < 7 * 128 / 2; idx += 256) sr[idx] = gr[idx];
    }
    __syncthreads();

    #pragma unroll
    for (int p = 0; p < 4; p++) {
        const int i_rank = (s << 10) + (p << 8) + tid;
        const int row = g_perm[m][i_rank];
        unsigned short rr[8];
        *reinterpret_cast<uint4*>(rr) = *reinterpret_cast<const uint4*>(&g_rank[m][row][0]);

        int pd[7];
        #pragma unroll
        for (int d = 0; d < 7; d++) {
            const unsigned short key = rr[d + 1];
            int k = 0;
            #pragma unroll
            for (int st = 64; st >= 1; st >>= 1)
                k += (ssr[d][k + st - 1] < key) ? st : 0;
            k += (ssr[d][k] < key);          // count can reach 128
            pd[d] = k;
        }

        int L = i_rank - (tt << 7);
        L = (L < 0) ? 0 : (L > 128 ? 128 : L);

        int cnt = 0;
        #pragma unroll
        for (int w = 0; w < TW; w++) {
            const unsigned a = sB[0][pd[0]][w] & sB[1][pd[1]][w] & sB[2][pd[2]][w];
            const unsigned b = sB[3][pd[3]][w] & sB[4][pd[4]][w] & sB[5][pd[5]][w];
            const int rem = L - (w << 5);
            const unsigned m0 = (rem <= 0) ? 0u
                               : (rem >= 32 ? 0xFFFFFFFFu : ((1u << rem) - 1u));
            cnt += __popc(a & b & sB[6][pd[6]][w] & m0);
        }
        atomicAdd(&g_counts[m * KN + i_rank], cnt);
    }
}

// ---------------------------------------------------------------------------
// FH) fused histogram + finalize (proven). g_counts now holds the dominated
//     count directly. Last-arriving block runs the W1 scan; resets scratch.
// ---------------------------------------------------------------------------
__global__ __launch_bounds__(1024) void kdm_finh(float* __restrict__ out) {
    const int tid = threadIdx.x, lane = tid & 31, wid = tid >> 5;

    cudaGridDependencySynchronize();

    {   // histogram phase
        const int slot = blockIdx.x * 1024 + tid;
        const int v = g_counts[slot];          // dominated count in [0, 8191]
        g_counts[slot] = 0;
        const int delta = (slot >= KN) ? -1 : 1;
        const unsigned mask = __match_any_sync(0xffffffffu, v);
        if ((int)(__ffs(mask) - 1) == lane)
            atomicAdd(&g_hd[v], delta * __popc(mask));
    }

    __threadfence();
    __syncthreads();
    __shared__ bool s_last;
    if (tid == 0) s_last = (atomicAdd(&g_ctr, 1u) == gridDim.x - 1);
    __syncthreads();
    if (!s_last) return;
    __threadfence();

    __shared__ int wsum[32];
    const int base = tid * 8;
    int d[8], tot = 0;
    #pragma unroll
    for (int k = 0; k < 8; k++) {
        d[k] = g_hd[base + k];
        g_hd[base + k] = 0;
        tot += d[k];
    }

    int v = tot;
    #pragma unroll
    for (int off = 1; off < 32; off <<= 1) {
        const int n = __shfl_up_sync(0xffffffffu, v, off);
        if (lane >= off) v += n;
    }
    if (lane == 31) wsum[wid] = v;
    __syncthreads();
    if (wid == 0) {
        int w = wsum[lane];
        #pragma unroll
        for (int off = 1; off < 32; off <<= 1) {
            const int n = __shfl_up_sync(0xffffffffu, w, off);
            if (lane >= off) w += n;
        }
        wsum[lane] = w;
    }
    __syncthreads();

    const int excl = v - tot + (wid ? wsum[wid - 1] : 0);
    int run = excl, acc = 0;
    #pragma unroll
    for (int k = 0; k < 8; k++) {
        run += d[k];
        acc += (run >= 0) ? run : -run;
    }

    #pragma unroll
    for (int off = 16; off; off >>= 1) acc += __shfl_down_sync(0xffffffffu, acc, off);
    __syncthreads();
    if (lane == 0) wsum[wid] = acc;
    __syncthreads();
    if (wid == 0) {
        int r = wsum[lane];
        #pragma unroll
        for (int off = 16; off; off >>= 1) r += __shfl_down_sync(0xffffffffu, r, off);
        if (lane == 0) {
            out[0] = (float)r / ((float)KN * (float)(KN - 1));
            g_ctr = 0;   // reset for next graph replay
        }
    }
}

// ---------------------------------------------------------------------------
template <typename F, typename... Args>
static void launch_pdl(F f, dim3 grid, dim3 block, Args... args) {
    cudaLaunchConfig_t cfg = {};
    cfg.gridDim  = grid;
    cfg.blockDim = block;
    cfg.dynamicSmemBytes = 0;
    cfg.stream = 0;
    cudaLaunchAttribute attr[1];
    attr[0].id = cudaLaunchAttributeProgrammaticStreamSerialization;
    attr[0].val.programmaticStreamSerializationAllowed = 1;
    cfg.attrs = attr;
    cfg.numAttrs = 1;
    cudaLaunchKernelEx(&cfg, f, args...);
}

extern "C" void kernel_launch(void* const* d_in, const int* in_sizes, int n_in,
                              void* d_out, int out_size) {
    const float* X  = (const float*)d_in[0];
    const float* Xh = (const float*)d_in[1];
    float* out = (float*)d_out;

    kdm_sort_seg<<<dim3(NSEG, 16), 256>>>(X, Xh);
    launch_pdl(kdm_rank, dim3(KN / 256, 16), dim3(256));
    launch_pdl(kdm_prep, dim3(NTILE, 7, 2),  dim3(128));
    launch_pdl(kdm_dom,  dim3(DOMB, 2),      dim3(256));
    launch_pdl(kdm_finh, dim3(2 * KN / 1024), dim3(1024), out);
}